// round 16
// baseline (speedup 1.0000x reference)
#include <cuda_runtime.h>
#include <cuda_fp16.h>

// ---------------------------------------------------------------------------
// setup_kernel folds params; layers 0-3 weights/biases are pre-broadcast to
// half2 (both lanes equal) so fused_kernel runs those layers entirely in
// packed half precision: 2 samples per half2 lane-pair, 4 samples per thread.
//   per layer: 8 HFMA2 + 4 tanh.approx.f16x2, no conversions.
// Layer 4 + final linear + quantum head stay f32 (undamped error path).
// Quantum head (3 MUFU.COS/sample):
//   q = K0 + K1 c0 + K2 c1 + (K3-K4) c0 c1 + K4 cos(x0-x1)
// ---------------------------------------------------------------------------

__device__ uint4  g_hw[6];   // [0..3]: layer l {w00,w01,w10,w11} as half2-bcast
                             // [4]: {b0_l0,b1_l0,b0_l1,b1_l1}  [5]: layers 2,3
__device__ float4 g_f4[4];   // [0]: W4  [1]: (B4_0,B4_1,wf0,wf1)
                             // [2]: (bff,K0,K1,K2)  [3]: (K3-K4,K4,0,0)

__global__ void setup_kernel(const float* __restrict__ Ws,
                             const float* __restrict__ bs,
                             const float* __restrict__ scales,
                             const float* __restrict__ shifts,
                             const float* __restrict__ Wf,
                             const float* __restrict__ bf,
                             const float* __restrict__ theta)
{
    if (threadIdx.x != 0) return;

    // ---- fused backbone params (scale/shift folded into next layer) -------
    float W[5][2][2], B[5][2];
#pragma unroll
    for (int l = 0; l < 5; l++) {
        float s0 = (l == 0) ? 1.0f : scales[2 * (l - 1) + 0];
        float s1 = (l == 0) ? 1.0f : scales[2 * (l - 1) + 1];
        float h0 = (l == 0) ? 0.0f : shifts[2 * (l - 1) + 0];
        float h1 = (l == 0) ? 0.0f : shifts[2 * (l - 1) + 1];
#pragma unroll
        for (int i = 0; i < 2; i++) {
            float w0 = Ws[4 * l + 2 * i + 0];
            float w1 = Ws[4 * l + 2 * i + 1];
            W[l][i][0] = w0 * s0;
            W[l][i][1] = w1 * s1;
            B[l][i] = w0 * h0 + w1 * h1 + bs[2 * l + i];
        }
    }
    float wf0 = Wf[0] * scales[8], wf1 = Wf[1] * scales[9];
    float bff = Wf[0] * shifts[8] + Wf[1] * shifts[9] + bf[0];

    // ---- quantum circuit matrix (RY layers + CZ, all real) ----------------
    float M[4][4];
#pragma unroll
    for (int i = 0; i < 4; i++)
#pragma unroll
        for (int j = 0; j < 4; j++) M[i][j] = (i == j) ? 1.0f : 0.0f;
#pragma unroll
    for (int d = 0; d < 2; d++) {
        float c0, s0, c1, s1;
        __sincosf(theta[2 * d + 0] * 0.5f, &s0, &c0);
        __sincosf(theta[2 * d + 1] * 0.5f, &s1, &c1);
#pragma unroll
        for (int q1 = 0; q1 < 2; q1++)
#pragma unroll
            for (int j = 0; j < 4; j++) {
                float r0 = M[2 * q1 + 0][j], r1 = M[2 * q1 + 1][j];
                M[2 * q1 + 0][j] = c0 * r0 - s0 * r1;
                M[2 * q1 + 1][j] = s0 * r0 + c0 * r1;
            }
#pragma unroll
        for (int q0 = 0; q0 < 2; q0++)
#pragma unroll
            for (int j = 0; j < 4; j++) {
                float r0 = M[q0][j], r1 = M[2 + q0][j];
                M[q0][j]     = c1 * r0 - s1 * r1;
                M[2 + q0][j] = s1 * r0 + c1 * r1;
            }
#pragma unroll
        for (int j = 0; j < 4; j++) M[3][j] = -M[3][j];
    }

    float a0 = M[0][0] * M[0][0], b0 = M[0][3] * M[0][3];
    float c0 = M[0][1] * M[0][1], d0 = M[0][2] * M[0][2];
    float e0 = M[0][1] * M[0][2] - M[0][0] * M[0][3];
    float a3 = M[3][0] * M[3][0], b3 = M[3][3] * M[3][3];
    float c3 = M[3][1] * M[3][1], d3 = M[3][2] * M[3][2];
    float e3 = M[3][1] * M[3][2] - M[3][0] * M[3][3];
    float K0 = 0.5f * ((a0 + b0 + c0 + d0) - (a3 + b3 + c3 + d3));
    float K1 = 0.5f * ((a0 - b0 - c0 + d0) - (a3 - b3 - c3 + d3));
    float K2 = 0.5f * ((a0 - b0 + c0 - d0) - (a3 - b3 + c3 - d3));
    float K3 = 0.5f * ((a0 + b0 - c0 - d0) - (a3 + b3 - c3 - d3));
    float K4 = e0 - e3;

    // ---- pack half2-broadcast params for layers 0-3 ------------------------
    auto pk = [](float v) -> unsigned int {
        __half2 h = __float2half2_rn(v);
        return *reinterpret_cast<unsigned int*>(&h);
    };
#pragma unroll
    for (int l = 0; l < 4; l++)
        g_hw[l] = make_uint4(pk(W[l][0][0]), pk(W[l][0][1]),
                             pk(W[l][1][0]), pk(W[l][1][1]));
    g_hw[4] = make_uint4(pk(B[0][0]), pk(B[0][1]), pk(B[1][0]), pk(B[1][1]));
    g_hw[5] = make_uint4(pk(B[2][0]), pk(B[2][1]), pk(B[3][0]), pk(B[3][1]));

    g_f4[0] = make_float4(W[4][0][0], W[4][0][1], W[4][1][0], W[4][1][1]);
    g_f4[1] = make_float4(B[4][0], B[4][1], wf0, wf1);
    g_f4[2] = make_float4(bff, K0, K1, K2);
    g_f4[3] = make_float4(K3 - K4, K4, 0.0f, 0.0f);
}

__device__ __forceinline__ float htanh(float x) {
    float y;
    asm("tanh.approx.f32 %0, %1;" : "=f"(y) : "f"(x));
    return y;
}
__device__ __forceinline__ __half2 htanh2(__half2 v) {
    unsigned int u = *reinterpret_cast<unsigned int*>(&v);
    asm("tanh.approx.f16x2 %0, %0;" : "+r"(u));
    return *reinterpret_cast<__half2*>(&u);
}
__device__ __forceinline__ __half2 u2h(unsigned int u) {
    return *reinterpret_cast<__half2*>(&u);
}

__global__ __launch_bounds__(256)
void fused_kernel(const float4* __restrict__ x, const float* __restrict__ xs,
                  float* __restrict__ out, int nquads, int n)
{
    __shared__ uint4  shw[6];
    __shared__ float4 shf[4];
    if (threadIdx.x < 6)  shw[threadIdx.x] = g_hw[threadIdx.x];
    if (threadIdx.x >= 32 && threadIdx.x < 36) shf[threadIdx.x - 32] = g_f4[threadIdx.x - 32];
    __syncthreads();

    int i = blockIdx.x * blockDim.x + threadIdx.x;   // 4 samples per thread
    if (i >= nquads) return;
    int s0 = i * 4;

    float4 xa, xb;
    if (s0 + 3 < n) {
        xa = __ldg(&x[2 * i + 0]);     // samples s0, s0+1
        xb = __ldg(&x[2 * i + 1]);     // samples s0+2, s0+3
    } else {
        float t[8];
#pragma unroll
        for (int k = 0; k < 4; k++) {
            int s = s0 + k;
            t[2 * k + 0] = (s < n) ? xs[2 * s + 0] : 0.0f;
            t[2 * k + 1] = (s < n) ? xs[2 * s + 1] : 0.0f;
        }
        xa = make_float4(t[0], t[1], t[2], t[3]);
        xb = make_float4(t[4], t[5], t[6], t[7]);
    }

    // pack: lane-pair (sampleA, sampleB) per half2; feature 0 and 1
    __half2 hA0 = __floats2half2_rn(xa.x, xa.z);
    __half2 hA1 = __floats2half2_rn(xa.y, xa.w);
    __half2 hB0 = __floats2half2_rn(xb.x, xb.z);
    __half2 hB1 = __floats2half2_rn(xb.y, xb.w);

    // Layers 0-3 fully packed: 8 HFMA2 + 4 MUFU per layer, no conversions.
#define LAYER_P(WV, BB0, BB1)                                           \
    {                                                                   \
        __half2 w00 = u2h((WV).x), w01 = u2h((WV).y);                   \
        __half2 w10 = u2h((WV).z), w11 = u2h((WV).w);                   \
        __half2 bb0 = u2h(BB0),    bb1 = u2h(BB1);                      \
        __half2 pA0 = __hfma2(w00, hA0, __hfma2(w01, hA1, bb0));        \
        __half2 pA1 = __hfma2(w10, hA0, __hfma2(w11, hA1, bb1));        \
        __half2 pB0 = __hfma2(w00, hB0, __hfma2(w01, hB1, bb0));        \
        __half2 pB1 = __hfma2(w10, hB0, __hfma2(w11, hB1, bb1));        \
        hA0 = htanh2(pA0); hA1 = htanh2(pA1);                           \
        hB0 = htanh2(pB0); hB1 = htanh2(pB1);                           \
    }

    LAYER_P(shw[0], shw[4].x, shw[4].y)
    LAYER_P(shw[1], shw[4].z, shw[4].w)
    LAYER_P(shw[2], shw[5].x, shw[5].y)
    LAYER_P(shw[3], shw[5].z, shw[5].w)
#undef LAYER_P

    // unpack to f32 for final layer
    float2 fA0 = __half22float2(hA0);   // (s0 f0, s1 f0)
    float2 fA1 = __half22float2(hA1);
    float2 fB0 = __half22float2(hB0);
    float2 fB1 = __half22float2(hB1);

    float4 W4 = shf[0], P1v = shf[1], P2v = shf[2], P3v = shf[3];

    float r[4];
    float h0s[4] = {fA0.x, fA0.y, fB0.x, fB0.y};
    float h1s[4] = {fA1.x, fA1.y, fB1.x, fB1.y};
    float us[4]  = {xa.x, xa.z, xb.x, xb.z};
    float vs[4]  = {xa.y, xa.w, xb.y, xb.w};

#pragma unroll
    for (int k = 0; k < 4; k++) {
        // Layer 4: f32 tanh (undamped error path)
        float p0 = fmaf(W4.x, h0s[k], fmaf(W4.y, h1s[k], P1v.x));
        float p1 = fmaf(W4.z, h0s[k], fmaf(W4.w, h1s[k], P1v.y));
        float h0 = htanh(p0), h1 = htanh(p1);
        float c = fmaf(P1v.z, h0, fmaf(P1v.w, h1, P2v.x));

        // quantum head
        float c0 = __cosf(us[k]);
        float c1 = __cosf(vs[k]);
        float cd = __cosf(us[k] - vs[k]);
        float q = fmaf(P2v.z, c0, P2v.y);
        q = fmaf(P2v.w, c1, q);
        q = fmaf(P3v.x, c0 * c1, q);
        q = fmaf(P3v.y, cd, q);

        r[k] = c + q;
    }

    if (s0 + 3 < n) {
        ((float4*)out)[i] = make_float4(r[0], r[1], r[2], r[3]);
    } else {
#pragma unroll
        for (int k = 0; k < 4; k++)
            if (s0 + k < n) out[s0 + k] = r[k];
    }
}

extern "C" void kernel_launch(void* const* d_in, const int* in_sizes, int n_in,
                              void* d_out, int out_size)
{
    const float* x      = (const float*)d_in[0];   // [N, 2]
    const float* Ws     = (const float*)d_in[1];
    const float* bs     = (const float*)d_in[2];
    const float* scales = (const float*)d_in[3];
    const float* shifts = (const float*)d_in[4];
    const float* Wf     = (const float*)d_in[5];
    const float* bf     = (const float*)d_in[6];
    const float* theta  = (const float*)d_in[7];

    int n = out_size;                      // N samples
    int nquads = (n + 3) / 4;

    setup_kernel<<<1, 32>>>(Ws, bs, scales, shifts, Wf, bf, theta);

    const int threads = 256;
    int blocks = (nquads + threads - 1) / threads;
    fused_kernel<<<blocks, threads>>>((const float4*)x, x, (float*)d_out,
                                      nquads, n);
}